// round 14
// baseline (speedup 1.0000x reference)
#include <cuda_runtime.h>
#include <cuda_bf16.h>
#include <math.h>
#include <cstdint>

#define BB 4
#define NN 32768
#define CC 256
#define HH 8
#define DD 32
#define GG 32
#define TOK1 64
#define BLKS1 (NN / TOK1)            // 512
#define NBLK1 (BB * BLKS1)           // 2048
#define PPB   BLKS1                  // 512 partials per batch (1 per CTA)
#define TOK3 64
#define BLKS3 (NN / TOK3)            // 512
#define NBLK3 (BB * BLKS3)           // 2048

typedef unsigned int u32;
typedef unsigned short u16;

// ---------------- device scratch ---------------------------------------------
__device__ u32   g_Bxs_hi[32768], g_Bxs_lo[32768];
__device__ u32   g_Bfx_hi[32768], g_Bfx_lo[32768];
__device__ float g_blog[256];
__device__ u16   g_w_hi[(size_t)BB * NN * 256];
__device__ u16   g_w_lo[(size_t)BB * NN * 256];
__device__ float g_part_tok[(size_t)NBLK1 * 256 * DD];
__device__ float g_part_norm[(size_t)NBLK1 * 256];
__device__ float g_tok_red[(size_t)BB * 256 * DD];
__device__ float g_norm_red[(size_t)BB * 256];
__device__ u32   g_Wt_hi[(size_t)BB * 32768];
__device__ u32   g_Wt_lo[(size_t)BB * 32768];

// ---------------- helpers -----------------------------------------------------
__device__ __forceinline__ u32 pack2bf(float x, float y) {
    __nv_bfloat162 h = __floats2bfloat162_rn(x, y);
    return *reinterpret_cast<u32*>(&h);
}
__device__ __forceinline__ void split2(float x, float y, u32& hi, u32& lo) {
    hi = pack2bf(x, y);
    const float hx = __uint_as_float((hi & 0xffffu) << 16);
    const float hy = __uint_as_float(hi & 0xffff0000u);
    lo = pack2bf(x - hx, y - hy);
}
__device__ __forceinline__ void mma16816(float* d, const u32* a, u32 b0, u32 b1) {
    asm volatile(
        "mma.sync.aligned.m16n8k16.row.col.f32.bf16.bf16.f32 "
        "{%0,%1,%2,%3}, {%4,%5,%6,%7}, {%8,%9}, {%0,%1,%2,%3};"
        : "+f"(d[0]), "+f"(d[1]), "+f"(d[2]), "+f"(d[3])
        : "r"(a[0]), "r"(a[1]), "r"(a[2]), "r"(a[3]), "r"(b0), "r"(b1));
}
__device__ __forceinline__ void ldsm4(u32* r, u32 saddr) {
    asm volatile(
        "ldmatrix.sync.aligned.m8n8.x4.shared.b16 {%0,%1,%2,%3}, [%4];"
        : "=r"(r[0]), "=r"(r[1]), "=r"(r[2]), "=r"(r[3]) : "r"(saddr));
}

// ---------------- K0: pack weight fragment images ----------------------------
__global__ void __launch_bounds__(256)
k0_pack(const float* __restrict__ Wx, const float* __restrict__ Ws,
        const float* __restrict__ bs, const float* __restrict__ bx,
        const float* __restrict__ Wfx)
{
    const int pid = blockIdx.x * 256 + threadIdx.x;
    const int img = pid >> 15;
    const int p = pid & 32767;
    const int r = p & 1, lane = (p >> 1) & 31, nt = (p >> 6) & 31, k16 = p >> 11;
    const int t = lane & 3, g = lane >> 2;
    const int k = k16 * 16 + r * 8 + 2 * t;
    const int n = nt * 8 + g;
    float v0, v1;
    if (img == 0) {
        const int h = n >> 5, gg = n & 31;
        float s0 = 0.f, s1 = 0.f;
#pragma unroll
        for (int d = 0; d < DD; ++d) {
            const float w = Ws[d * GG + gg];
            s0 = fmaf(Wx[k * 256 + h * 32 + d], w, s0);
            s1 = fmaf(Wx[(k + 1) * 256 + h * 32 + d], w, s1);
        }
        v0 = s0; v1 = s1;
    } else {
        v0 = Wfx[k * 256 + n];
        v1 = Wfx[(k + 1) * 256 + n];
    }
    u32 hi, lo;
    split2(v0, v1, hi, lo);
    if (img == 0) { g_Bxs_hi[p] = hi; g_Bxs_lo[p] = lo; }
    else          { g_Bfx_hi[p] = hi; g_Bfx_lo[p] = lo; }

    if (blockIdx.x == 0) {
        const int hg = threadIdx.x;
        const int h = hg >> 5, gg = hg & 31;
        float s = bs[gg];
#pragma unroll
        for (int d = 0; d < DD; ++d)
            s = fmaf(bx[h * 32 + d], Ws[d * GG + gg], s);
        g_blog[hg] = s;
    }
}

// ---------------- K1: LN + merged tensor GEMM + softmax + partials ------------
#define S1_ALO   33792
#define S1_F     67584
#define S1_INVT  (S1_F + 64 * 264 * 4)        // 135168
#define S1_TOTAL (S1_INVT + 64)

__global__ void __launch_bounds__(512, 1)
k1_dispatch(const float* __restrict__ fx,
            const float* __restrict__ ln_g, const float* __restrict__ ln_b,
            const float* __restrict__ bfx,  const float* __restrict__ tempp)
{
    extern __shared__ char smem[];
    u32*   sAh   = reinterpret_cast<u32*>(smem);
    u32*   sAl   = reinterpret_cast<u32*>(smem + S1_ALO);
    float* sW    = reinterpret_cast<float*>(smem);           // overlay after GEMM
    float* sF    = reinterpret_cast<float*>(smem + S1_F);
    float* sInvt = reinterpret_cast<float*>(smem + S1_INVT);

    const int tid  = threadIdx.x;
    const int w    = tid >> 5;
    const int lane = tid & 31;
    const int g    = lane >> 2, t = lane & 3;
    const int gi   = w >> 3;              // 0: fx_mid GEMM, 1: logits GEMM
    const int h    = w & 7;               // head
    const int batch = blockIdx.x / BLKS1;
    const int n0    = (blockIdx.x % BLKS1) * TOK1;

    if (tid < HH) sInvt[tid] = 1.0f / tempp[tid];

    const float* fxp = fx + ((size_t)batch * NN + n0) * CC;
    for (int idx = tid * 4; idx < TOK1 * CC; idx += 2048) {
        const int row = idx >> 8, col = idx & 255;
        *reinterpret_cast<float4*>(&sF[row * 264 + col]) =
            *reinterpret_cast<const float4*>(&fxp[idx]);
    }
    __syncthreads();

    for (int rrow = w * 4; rrow < w * 4 + 4; ++rrow) {
        float s = 0.f, s2 = 0.f;
#pragma unroll
        for (int c = lane; c < CC; c += 32) {
            const float v = sF[rrow * 264 + c];
            s += v; s2 += v * v;
        }
#pragma unroll
        for (int o = 16; o; o >>= 1) {
            s  += __shfl_xor_sync(0xffffffffu, s,  o);
            s2 += __shfl_xor_sync(0xffffffffu, s2, o);
        }
        const float mu = s * (1.f / CC);
        const float rstd = rsqrtf(s2 * (1.f / CC) - mu * mu + 1e-5f);
#pragma unroll
        for (int c = lane; c < CC; c += 32) {
            const float v = sF[rrow * 264 + c];
            sF[rrow * 264 + c] = (v - mu) * rstd * ln_g[c] + ln_b[c];
        }
    }
    __syncthreads();

    for (int idx = tid; idx < 8192; idx += 512) {
        const int row = idx >> 7, cp = idx & 127;
        const float2 v = *reinterpret_cast<const float2*>(&sF[row * 264 + cp * 2]);
        u32 hi, lo;
        split2(v.x, v.y, hi, lo);
        sAh[row * 132 + cp] = hi;
        sAl[row * 132 + cp] = lo;
    }
    __syncthreads();

    const int jj_ = lane >> 3, rr_ = lane & 7;
    const int rowsel = (jj_ & 1) * 8 + rr_;
    const int colw   = (jj_ >> 1) * 4;
    const u32 aShB = (u32)__cvta_generic_to_shared(sAh);
    const u32 aSlB = (u32)__cvta_generic_to_shared(sAl);
    u32 offA[4];
#pragma unroll
    for (int mt = 0; mt < 4; ++mt)
        offA[mt] = (u32)(((mt * 16 + rowsel) * 132 + colw) * 4);

    float acc[4][4][4];
#pragma unroll
    for (int mt = 0; mt < 4; ++mt)
#pragma unroll
        for (int nt = 0; nt < 4; ++nt)
#pragma unroll
            for (int i = 0; i < 4; ++i) acc[mt][nt][i] = 0.f;

    const uint2* B2H = reinterpret_cast<const uint2*>(gi ? g_Bxs_hi : g_Bfx_hi);
    const uint2* B2L = reinterpret_cast<const uint2*>(gi ? g_Bxs_lo : g_Bfx_lo);

    {
        uint2 bh[4], bl[4];
#pragma unroll
        for (int nt = 0; nt < 4; ++nt) {
            bh[nt] = B2H[(h * 4 + nt) * 32 + lane];
            bl[nt] = B2L[(h * 4 + nt) * 32 + lane];
        }
#pragma unroll 1
        for (int k16 = 0; k16 < 16; ++k16) {
            uint2 nh[4], nl[4];
            if (k16 < 15) {
#pragma unroll
                for (int nt = 0; nt < 4; ++nt) {
                    nh[nt] = B2H[((k16 + 1) * 32 + h * 4 + nt) * 32 + lane];
                    nl[nt] = B2L[((k16 + 1) * 32 + h * 4 + nt) * 32 + lane];
                }
            }
            u32 a[4][4];
#pragma unroll
            for (int mt = 0; mt < 4; ++mt)
                ldsm4(a[mt], aShB + offA[mt] + (u32)(k16 * 32));
#pragma unroll
            for (int mt = 0; mt < 4; ++mt)
#pragma unroll
                for (int nt = 0; nt < 4; ++nt)
                    mma16816(acc[mt][nt], a[mt], bh[nt].x, bh[nt].y);
#pragma unroll
            for (int mt = 0; mt < 4; ++mt)
#pragma unroll
                for (int nt = 0; nt < 4; ++nt)
                    mma16816(acc[mt][nt], a[mt], bl[nt].x, bl[nt].y);
#pragma unroll
            for (int mt = 0; mt < 4; ++mt)
                ldsm4(a[mt], aSlB + offA[mt] + (u32)(k16 * 32));
#pragma unroll
            for (int mt = 0; mt < 4; ++mt)
#pragma unroll
                for (int nt = 0; nt < 4; ++nt)
                    mma16816(acc[mt][nt], a[mt], bh[nt].x, bh[nt].y);
#pragma unroll
            for (int nt = 0; nt < 4; ++nt) { bh[nt] = nh[nt]; bl[nt] = nl[nt]; }
        }
    }
    __syncthreads();

    if (gi == 0) {
#pragma unroll
        for (int mt = 0; mt < 4; ++mt)
#pragma unroll
            for (int nt = 0; nt < 4; ++nt) {
                const int r0 = mt * 16 + g;
                const int c = h * 32 + nt * 8 + 2 * t;
                const float b0 = bfx[c], b1 = bfx[c + 1];
                *reinterpret_cast<float2*>(&sF[r0 * 264 + c]) =
                    make_float2(acc[mt][nt][0] + b0, acc[mt][nt][1] + b1);
                *reinterpret_cast<float2*>(&sF[(r0 + 8) * 264 + c]) =
                    make_float2(acc[mt][nt][2] + b0, acc[mt][nt][3] + b1);
            }
    } else {
        const float iv = sInvt[h];
#pragma unroll
        for (int mt = 0; mt < 4; ++mt)
#pragma unroll
            for (int nt = 0; nt < 4; ++nt) {
                const int c = h * 32 + nt * 8 + 2 * t;
                const float b0 = g_blog[c], b1 = g_blog[c + 1];
                acc[mt][nt][0] = (acc[mt][nt][0] + b0) * iv;
                acc[mt][nt][1] = (acc[mt][nt][1] + b1) * iv;
                acc[mt][nt][2] = (acc[mt][nt][2] + b0) * iv;
                acc[mt][nt][3] = (acc[mt][nt][3] + b1) * iv;
            }
#pragma unroll
        for (int mt = 0; mt < 4; ++mt)
#pragma unroll
            for (int rv = 0; rv < 2; ++rv) {
                float mx = -1e30f;
#pragma unroll
                for (int j = 0; j < 4; ++j) {
                    mx = fmaxf(mx, acc[mt][j][rv * 2]);
                    mx = fmaxf(mx, acc[mt][j][rv * 2 + 1]);
                }
                mx = fmaxf(mx, __shfl_xor_sync(0xffffffffu, mx, 1));
                mx = fmaxf(mx, __shfl_xor_sync(0xffffffffu, mx, 2));
                float sum = 0.f;
#pragma unroll
                for (int j = 0; j < 4; ++j) {
                    float e0 = __expf(acc[mt][j][rv * 2] - mx);
                    float e1 = __expf(acc[mt][j][rv * 2 + 1] - mx);
                    acc[mt][j][rv * 2] = e0;
                    acc[mt][j][rv * 2 + 1] = e1;
                    sum += e0 + e1;
                }
                sum += __shfl_xor_sync(0xffffffffu, sum, 1);
                sum += __shfl_xor_sync(0xffffffffu, sum, 2);
                const float inv = 1.0f / sum;
#pragma unroll
                for (int j = 0; j < 4; ++j) {
                    acc[mt][j][rv * 2] *= inv;
                    acc[mt][j][rv * 2 + 1] *= inv;
                }
            }
        u32* gwh = reinterpret_cast<u32*>(g_w_hi);
        u32* gwl = reinterpret_cast<u32*>(g_w_lo);
#pragma unroll
        for (int mt = 0; mt < 4; ++mt)
#pragma unroll
            for (int nt = 0; nt < 4; ++nt) {
                const int r0 = mt * 16 + g;
                const int c = h * 32 + nt * 8 + 2 * t;
                *reinterpret_cast<float2*>(&sW[r0 * 264 + c]) =
                    make_float2(acc[mt][nt][0], acc[mt][nt][1]);
                *reinterpret_cast<float2*>(&sW[(r0 + 8) * 264 + c]) =
                    make_float2(acc[mt][nt][2], acc[mt][nt][3]);
                u32 hi, lo;
                split2(acc[mt][nt][0], acc[mt][nt][1], hi, lo);
                size_t bi = (((size_t)batch * NN + n0 + r0) * 256 + c) >> 1;
                gwh[bi] = hi; gwl[bi] = lo;
                split2(acc[mt][nt][2], acc[mt][nt][3], hi, lo);
                bi = (((size_t)batch * NN + n0 + r0 + 8) * 256 + c) >> 1;
                gwh[bi] = hi; gwl[bi] = lo;
            }
    }
    __syncthreads();

    // partial accumulation: warp = (half, head); combine halves via smem.
    {
        const int hh = w & 7;
        const int half = w >> 3;
        const int rbase = half * 32;
        float4 accT[8];
#pragma unroll
        for (int j = 0; j < 8; ++j) accT[j] = make_float4(0.f, 0.f, 0.f, 0.f);
        float accN = 0.f;
#pragma unroll 4
        for (int rr = 0; rr < 32; ++rr) {
            const int row = rbase + rr;
            const float wv = sW[row * 264 + hh * 32 + lane];
            accN += wv;
#pragma unroll
            for (int j = 0; j < 8; ++j) {
                const float4 f = *reinterpret_cast<const float4*>(
                    &sF[row * 264 + hh * 32 + j * 4]);
                accT[j].x = fmaf(wv, f.x, accT[j].x);
                accT[j].y = fmaf(wv, f.y, accT[j].y);
                accT[j].z = fmaf(wv, f.z, accT[j].z);
                accT[j].w = fmaf(wv, f.w, accT[j].w);
            }
        }
        __syncthreads();
        float* sX  = reinterpret_cast<float*>(smem);
        float* sXn = sX + 8192;
        if (half == 1) {
            float4* dst = reinterpret_cast<float4*>(&sX[(hh * 32 + lane) * 32]);
#pragma unroll
            for (int j = 0; j < 8; ++j) dst[j] = accT[j];
            sXn[hh * 32 + lane] = accN;
        }
        __syncthreads();
        if (half == 0) {
            const float4* src = reinterpret_cast<const float4*>(
                &sX[(hh * 32 + lane) * 32]);
            float4* pt = reinterpret_cast<float4*>(
                g_part_tok + ((size_t)blockIdx.x * 256 + hh * 32 + lane) * DD);
#pragma unroll
            for (int j = 0; j < 8; ++j) {
                float4 v = src[j];
                v.x += accT[j].x; v.y += accT[j].y;
                v.z += accT[j].z; v.w += accT[j].w;
                pt[j] = v;
            }
            g_part_norm[(size_t)blockIdx.x * 256 + hh * 32 + lane] =
                accN + sXn[hh * 32 + lane];
        }
    }
}

// ---------------- K2a: parallel partial reduce ---------------------------------
__global__ void __launch_bounds__(256)
k2a_reduce()
{
    __shared__ float red[8][33];
    __shared__ float rn[256];
    const int b  = blockIdx.x >> 8;
    const int hg = blockIdx.x & 255;
    const int tid = threadIdx.x;
    const int d = tid & 31, ck = tid >> 5;

    const float* base = g_part_tok + ((size_t)(b * PPB) * 256 + hg) * DD + d;
    float s = 0.f;
#pragma unroll 8
    for (int i = 0; i < PPB / 8; ++i)
        s += base[(size_t)(ck * (PPB / 8) + i) * (256 * DD)];
    red[ck][d] = s;

    float ns = 0.f;
#pragma unroll
    for (int j = 0; j < PPB / 256; ++j)
        ns += g_part_norm[(size_t)(b * PPB + tid * (PPB / 256) + j) * 256 + hg];
    rn[tid] = ns;
    __syncthreads();

    if (tid < 32) {
        float tot = 0.f;
#pragma unroll
        for (int c = 0; c < 8; ++c) tot += red[c][tid];
        g_tok_red[((size_t)b * 256 + hg) * DD + tid] = tot;
        float nsum = 0.f;
#pragma unroll
        for (int c = 0; c < 8; ++c) nsum += rn[tid + c * 32];
#pragma unroll
        for (int o = 16; o; o >>= 1) nsum += __shfl_xor_sync(0xffffffffu, nsum, o);
        if (tid == 0) g_norm_red[(size_t)b * 256 + hg] = nsum;
    }
}

// ---------------- K2b: attention + MLP + Wt frag images ------------------------
__global__ void __launch_bounds__(1024)
k2_tokens(const float* __restrict__ Wq, const float* __restrict__ Wk,
          const float* __restrict__ Wv,
          const float* __restrict__ tln_g, const float* __restrict__ tln_b,
          const float* __restrict__ W1, const float* __restrict__ b1,
          const float* __restrict__ W2, const float* __restrict__ b2,
          const float* __restrict__ Wo)
{
    const int b = blockIdx.x / HH;
    const int h = blockIdx.x % HH;
    const int tid = threadIdx.x;
    const int g = tid >> 5, d = tid & 31;

    __shared__ float s_st[GG][DD + 1];
    __shared__ float s_q[GG][DD + 1], s_k[GG][DD + 1], s_v[GG][DD + 1];
    __shared__ float s_attn[GG][GG + 1];
    __shared__ float s_h1[GG][4 * DD];
    __shared__ float s_tok2[GG][DD + 1];

    const float st = g_tok_red[((size_t)b * 256 + h * GG + g) * DD + d] /
                     (g_norm_red[(size_t)b * 256 + h * GG + g] + 1e-5f);
    s_st[g][d] = st;
    __syncthreads();

    float q = 0.f, kk = 0.f, vv = 0.f;
#pragma unroll
    for (int dd2 = 0; dd2 < DD; ++dd2) {
        const float sv = s_st[g][dd2];
        q  = fmaf(sv, Wq[dd2 * DD + d], q);
        kk = fmaf(sv, Wk[dd2 * DD + d], kk);
        vv = fmaf(sv, Wv[dd2 * DD + d], vv);
    }
    s_q[g][d] = q; s_k[g][d] = kk; s_v[g][d] = vv;
    __syncthreads();

    {
        const int kidx = d;
        float lg = 0.f;
#pragma unroll
        for (int dd2 = 0; dd2 < DD; ++dd2)
            lg = fmaf(s_q[g][dd2], s_k[kidx][dd2], lg);
        lg *= 0.17677669529663687f;
        float m = lg;
#pragma unroll
        for (int o = 16; o; o >>= 1) m = fmaxf(m, __shfl_xor_sync(0xffffffffu, m, o));
        const float e = __expf(lg - m);
        float ssum = e;
#pragma unroll
        for (int o = 16; o; o >>= 1) ssum += __shfl_xor_sync(0xffffffffu, ssum, o);
        s_attn[g][kidx] = e / ssum;
    }
    __syncthreads();

    float ot = st;
#pragma unroll
    for (int kidx = 0; kidx < GG; ++kidx)
        ot = fmaf(s_attn[g][kidx], s_v[kidx][d], ot);

    float s1 = ot, s2o = ot * ot;
#pragma unroll
    for (int o = 16; o; o >>= 1) {
        s1  += __shfl_xor_sync(0xffffffffu, s1,  o);
        s2o += __shfl_xor_sync(0xffffffffu, s2o, o);
    }
    const float mu = s1 * (1.f / DD);
    const float rstd = rsqrtf(s2o * (1.f / DD) - mu * mu + 1e-5f);
    const float hn = (ot - mu) * rstd * tln_g[d] + tln_b[d];
    __syncthreads();
    s_st[g][d] = hn;
    __syncthreads();

#pragma unroll
    for (int jj = 0; jj < 4; ++jj) {
        const int j = d + 32 * jj;
        float a = b1[j];
#pragma unroll
        for (int dd2 = 0; dd2 < DD; ++dd2)
            a = fmaf(s_st[g][dd2], W1[dd2 * (4 * DD) + j], a);
        a = 0.5f * a * (1.0f + erff(a * 0.70710678118654752f));
        s_h1[g][j] = a;
    }
    __syncthreads();

    float tk = b2[d];
#pragma unroll
    for (int j = 0; j < 4 * DD; ++j)
        tk = fmaf(s_h1[g][j], W2[j * DD + d], tk);
    tk += ot;
    s_tok2[g][d] = tk;
    __syncthreads();

    for (int idx = tid; idx < 4096; idx += 1024) {
        const int r = idx & 1;
        const int lane2 = (idx >> 1) & 31;
        const int nt = (idx >> 6) & 31;
        const int k16i = idx >> 11;
        const int t2 = lane2 & 3, g2 = lane2 >> 2;
        const int gl0 = k16i * 16 + r * 8 + 2 * t2;
        const int n = nt * 8 + g2;
        float v0 = 0.f, v1 = 0.f;
#pragma unroll
        for (int dd2 = 0; dd2 < DD; ++dd2) {
            const float wov = Wo[(h * DD + dd2) * CC + n];
            v0 = fmaf(s_tok2[gl0][dd2], wov, v0);
            v1 = fmaf(s_tok2[gl0 + 1][dd2], wov, v1);
        }
        u32 hi, lo;
        split2(v0, v1, hi, lo);
        const size_t oi = (size_t)b * 32768 +
            ((((size_t)(h * 2 + k16i) * 32 + nt) * 32 + lane2) * 2 + r);
        g_Wt_hi[oi] = hi;
        g_Wt_lo[oi] = lo;
    }
}

// ---------------- K3: out = w @ Wt + bo + LN(fx), TOK3=64, 2 CTAs/SM ----------
// smem: sA_hi u32[64][132] | sA_lo | sMu[64] | sRs[64]  (~68KB)
#define S3_ALO   33792
#define S3_MU    67584
#define S3_RS    (S3_MU + 256)
#define S3_TOTAL (S3_RS + 256)

__global__ void __launch_bounds__(512, 2)
k3_tc(const float* __restrict__ fx,
      const float* __restrict__ ln_g, const float* __restrict__ ln_b,
      const float* __restrict__ bo,  float* __restrict__ out)
{
    extern __shared__ char smem[];
    u32*   sAh = reinterpret_cast<u32*>(smem);
    u32*   sAl = reinterpret_cast<u32*>(smem + S3_ALO);
    float* sMu = reinterpret_cast<float*>(smem + S3_MU);
    float* sRs = reinterpret_cast<float*>(smem + S3_RS);

    const int tid  = threadIdx.x;
    const int w    = tid >> 5;
    const int lane = tid & 31;
    const int g    = lane >> 2, t = lane & 3;
    const int wr   = w >> 2;          // 0..3: 16-row group
    const int wn   = w & 3;           // 0..3: 32-col group within ch half
    const int batch = blockIdx.x / BLKS3;
    const int n0    = (blockIdx.x % BLKS3) * TOK3;

    {
        const u32* gwh = reinterpret_cast<const u32*>(g_w_hi) +
                         (((size_t)batch * NN + n0) * 256 >> 1);
        const u32* gwl = reinterpret_cast<const u32*>(g_w_lo) +
                         (((size_t)batch * NN + n0) * 256 >> 1);
        for (int idx = tid; idx < 64 * 128; idx += 512) {
            const int row = idx >> 7, cp = idx & 127;
            sAh[row * 132 + cp] = gwh[row * 128 + cp];
            sAl[row * 132 + cp] = gwl[row * 128 + cp];
        }
    }

    // LN stats: warp w handles rows w*4..+4
    for (int i = 0; i < 4; ++i) {
        const int row = w * 4 + i;
        const float* rp = fx + ((size_t)batch * NN + n0 + row) * CC + lane * 8;
        const float4 f1 = *reinterpret_cast<const float4*>(rp);
        const float4 f2 = *reinterpret_cast<const float4*>(rp + 4);
        float s = f1.x + f1.y + f1.z + f1.w + f2.x + f2.y + f2.z + f2.w;
        float s2 = f1.x * f1.x + f1.y * f1.y + f1.z * f1.z + f1.w * f1.w +
                   f2.x * f2.x + f2.y * f2.y + f2.z * f2.z + f2.w * f2.w;
#pragma unroll
        for (int o = 16; o; o >>= 1) {
            s  += __shfl_xor_sync(0xffffffffu, s,  o);
            s2 += __shfl_xor_sync(0xffffffffu, s2, o);
        }
        if (lane == 0) {
            const float mu = s * (1.f / CC);
            sMu[row] = mu;
            sRs[row] = rsqrtf(s2 * (1.f / CC) - mu * mu + 1e-5f);
        }
    }
    __syncthreads();

    const int jj_ = lane >> 3, rr_ = lane & 7;
    const int rowsel = (jj_ & 1) * 8 + rr_;
    const int colw   = (jj_ >> 1) * 4;
    const u32 aShB = (u32)__cvta_generic_to_shared(sAh);
    const u32 aSlB = (u32)__cvta_generic_to_shared(sAl);
    const u32 offA = (u32)(((wr * 16 + rowsel) * 132 + colw) * 4);

    const uint2* BhG = reinterpret_cast<const uint2*>(g_Wt_hi + (size_t)batch * 32768);
    const uint2* BlG = reinterpret_cast<const uint2*>(g_Wt_lo + (size_t)batch * 32768);

#pragma unroll 1
    for (int ch = 0; ch < 2; ++ch) {
        float acc[4][4];
#pragma unroll
        for (int nt = 0; nt < 4; ++nt)
#pragma unroll
            for (int i = 0; i < 4; ++i) acc[nt][i] = 0.f;

        // seg 0: Bh with Ah + Al; seg 1: Bl with Ah. B direct from L2.
#pragma unroll 1
        for (int seg = 0; seg < 2; ++seg) {
            const uint2* B = (seg == 0) ? BhG : BlG;
#pragma unroll 1
            for (int k16 = 0; k16 < 16; ++k16) {
                uint2 b[4];
#pragma unroll
                for (int nt = 0; nt < 4; ++nt)
                    b[nt] = B[(k16 * 32 + ch * 16 + wn * 4 + nt) * 32 + lane];
                u32 a[4];
                ldsm4(a, aShB + offA + (u32)(k16 * 32));
#pragma unroll
                for (int nt = 0; nt < 4; ++nt)
                    mma16816(acc[nt], a, b[nt].x, b[nt].y);
                if (seg == 0) {
                    ldsm4(a, aSlB + offA + (u32)(k16 * 32));
#pragma unroll
                    for (int nt = 0; nt < 4; ++nt)
                        mma16816(acc[nt], a, b[nt].x, b[nt].y);
                }
            }
        }

        // epilogue for this ch
#pragma unroll
        for (int nt = 0; nt < 4; ++nt) {
            const int c = ch * 128 + wn * 32 + nt * 8 + 2 * t;
            const float bo0 = bo[c], bo1 = bo[c + 1];
            const float lg0 = ln_g[c], lg1 = ln_g[c + 1];
            const float lb0 = ln_b[c], lb1 = ln_b[c + 1];
#pragma unroll
            for (int rv = 0; rv < 2; ++rv) {
                const int row = wr * 16 + g + rv * 8;
                const size_t go = ((size_t)batch * NN + n0 + row) * 256 + c;
                const float2 fv = *reinterpret_cast<const float2*>(&fx[go]);
                const float mu = sMu[row], rs = sRs[row];
                float2 o;
                o.x = acc[nt][rv * 2]     + bo0 + (fv.x - mu) * rs * lg0 + lb0;
                o.y = acc[nt][rv * 2 + 1] + bo1 + (fv.y - mu) * rs * lg1 + lb1;
                *reinterpret_cast<float2*>(&out[go]) = o;
            }
        }
    }
}

// ---------------- launch -------------------------------------------------------
extern "C" void kernel_launch(void* const* d_in, const int* in_sizes, int n_in,
                              void* d_out, int out_size)
{
    const float* fx    = (const float*)d_in[0];
    const float* ln_g  = (const float*)d_in[1];
    const float* ln_b  = (const float*)d_in[2];
    const float* Wx    = (const float*)d_in[3];
    const float* bx    = (const float*)d_in[4];
    const float* Wfx   = (const float*)d_in[5];
    const float* bfx   = (const float*)d_in[6];
    const float* Ws    = (const float*)d_in[7];
    const float* bs    = (const float*)d_in[8];
    const float* tempp = (const float*)d_in[9];
    const float* Wq    = (const float*)d_in[10];
    const float* Wk    = (const float*)d_in[11];
    const float* Wv    = (const float*)d_in[12];
    const float* tln_g = (const float*)d_in[13];
    const float* tln_b = (const float*)d_in[14];
    const float* W1    = (const float*)d_in[15];
    const float* b1    = (const float*)d_in[16];
    const float* W2    = (const float*)d_in[17];
    const float* b2    = (const float*)d_in[18];
    const float* Wo    = (const float*)d_in[19];
    const float* bo    = (const float*)d_in[20];
    float* out = (float*)d_out;

    static int s_init = 0;
    if (!s_init) {
        cudaFuncSetAttribute(k1_dispatch, cudaFuncAttributeMaxDynamicSharedMemorySize, S1_TOTAL);
        cudaFuncSetAttribute(k3_tc, cudaFuncAttributeMaxDynamicSharedMemorySize, S3_TOTAL);
        s_init = 1;
    }

    k0_pack<<<256, 256>>>(Wx, Ws, bs, bx, Wfx);
    k1_dispatch<<<NBLK1, 512, S1_TOTAL>>>(fx, ln_g, ln_b, bfx, tempp);
    k2a_reduce<<<BB * 256, 256>>>();
    k2_tokens<<<BB * HH, 1024>>>(Wq, Wk, Wv, tln_g, tln_b, W1, b1, W2, b2, Wo);
    k3_tc<<<NBLK3, 512, S3_TOTAL>>>(fx, ln_g, ln_b, bo, out);
}

// round 15
// speedup vs baseline: 1.4511x; 1.4511x over previous
#include <cuda_runtime.h>
#include <cuda_bf16.h>
#include <math.h>
#include <cstdint>

#define BB 4
#define NN 32768
#define CC 256
#define HH 8
#define DD 32
#define GG 32
#define TOK1 64
#define BLKS1 (NN / TOK1)            // 512
#define NBLK1 (BB * BLKS1)           // 2048
#define PPB   BLKS1                  // 512 partials per batch
#define TOK3 64
#define BLKS3 (NN / TOK3)            // 512
#define NBLK3 (BB * BLKS3)           // 2048

typedef unsigned int u32;
typedef unsigned short u16;

// ---------------- device scratch ---------------------------------------------
__device__ u32   g_Bxs[32768];                      // WxWs frag image (bf16x2)
__device__ u32   g_Bfx[32768];                      // Wfx frag image
__device__ float g_blog[256];
__device__ u16   g_w[(size_t)BB * NN * 256];        // slice_w bf16 [b][n][hg]
__device__ float g_part_tok[(size_t)NBLK1 * 256 * DD];
__device__ float g_part_norm[(size_t)NBLK1 * 256];
__device__ float g_tok_red[(size_t)BB * 256 * DD];
__device__ float g_norm_red[(size_t)BB * 256];
__device__ u32   g_Wt[(size_t)BB * 32768];          // Wt frag image per batch

// ---------------- helpers -----------------------------------------------------
__device__ __forceinline__ u32 pack2bf(float x, float y) {
    __nv_bfloat162 h = __floats2bfloat162_rn(x, y);
    return *reinterpret_cast<u32*>(&h);
}
__device__ __forceinline__ void mma16816(float* d, const u32* a, u32 b0, u32 b1) {
    asm volatile(
        "mma.sync.aligned.m16n8k16.row.col.f32.bf16.bf16.f32 "
        "{%0,%1,%2,%3}, {%4,%5,%6,%7}, {%8,%9}, {%0,%1,%2,%3};"
        : "+f"(d[0]), "+f"(d[1]), "+f"(d[2]), "+f"(d[3])
        : "r"(a[0]), "r"(a[1]), "r"(a[2]), "r"(a[3]), "r"(b0), "r"(b1));
}
__device__ __forceinline__ void ldsm4(u32* r, u32 saddr) {
    asm volatile(
        "ldmatrix.sync.aligned.m8n8.x4.shared.b16 {%0,%1,%2,%3}, [%4];"
        : "=r"(r[0]), "=r"(r[1]), "=r"(r[2]), "=r"(r[3]) : "r"(saddr));
}

// ---------------- K0: pack weight fragment images ----------------------------
__global__ void __launch_bounds__(256)
k0_pack(const float* __restrict__ Wx, const float* __restrict__ Ws,
        const float* __restrict__ bs, const float* __restrict__ bx,
        const float* __restrict__ Wfx)
{
    const int pid = blockIdx.x * 256 + threadIdx.x;
    const int img = pid >> 15;
    const int p = pid & 32767;
    const int r = p & 1, lane = (p >> 1) & 31, nt = (p >> 6) & 31, k16 = p >> 11;
    const int t = lane & 3, g = lane >> 2;
    const int k = k16 * 16 + r * 8 + 2 * t;
    const int n = nt * 8 + g;
    float v0, v1;
    if (img == 0) {
        const int h = n >> 5, gg = n & 31;
        float s0 = 0.f, s1 = 0.f;
#pragma unroll
        for (int d = 0; d < DD; ++d) {
            const float w = Ws[d * GG + gg];
            s0 = fmaf(Wx[k * 256 + h * 32 + d], w, s0);
            s1 = fmaf(Wx[(k + 1) * 256 + h * 32 + d], w, s1);
        }
        v0 = s0; v1 = s1;
    } else {
        v0 = Wfx[k * 256 + n];
        v1 = Wfx[(k + 1) * 256 + n];
    }
    const u32 hv = pack2bf(v0, v1);
    if (img == 0) g_Bxs[p] = hv;
    else          g_Bfx[p] = hv;

    if (blockIdx.x == 0) {
        const int hg = threadIdx.x;
        const int h = hg >> 5, gg = hg & 31;
        float s = bs[gg];
#pragma unroll
        for (int d = 0; d < DD; ++d)
            s = fmaf(bx[h * 32 + d], Ws[d * GG + gg], s);
        g_blog[hg] = s;
    }
}

// ---------------- K1: LN + tensor GEMMs + softmax + partials ------------------
// smem: sA u32[64][132] (bf16x2 image) | sF f32[64][264] | sInvt f32[8]
// after GEMM, [0, 67584) region is overlaid by sW f32[64][264].
#define S1_F     67584
#define S1_INVT  (S1_F + 64 * 264 * 4)        // 135168
#define S1_TOTAL (S1_INVT + 64)

__global__ void __launch_bounds__(512, 1)
k1_dispatch(const float* __restrict__ fx,
            const float* __restrict__ ln_g, const float* __restrict__ ln_b,
            const float* __restrict__ bfx,  const float* __restrict__ tempp)
{
    extern __shared__ char smem[];
    u32*   sA    = reinterpret_cast<u32*>(smem);
    float* sW    = reinterpret_cast<float*>(smem);           // overlay after GEMM
    float* sF    = reinterpret_cast<float*>(smem + S1_F);
    float* sInvt = reinterpret_cast<float*>(smem + S1_INVT);

    const int tid  = threadIdx.x;
    const int w    = tid >> 5;
    const int lane = tid & 31;
    const int g    = lane >> 2, t = lane & 3;
    const int gi   = w >> 3;              // 0: fx_mid GEMM, 1: logits GEMM
    const int h    = w & 7;               // head
    const int batch = blockIdx.x / BLKS1;
    const int n0    = (blockIdx.x % BLKS1) * TOK1;

    if (tid < HH) sInvt[tid] = 1.0f / tempp[tid];

    const float* fxp = fx + ((size_t)batch * NN + n0) * CC;
    for (int idx = tid * 4; idx < TOK1 * CC; idx += 2048) {
        const int row = idx >> 8, col = idx & 255;
        *reinterpret_cast<float4*>(&sF[row * 264 + col]) =
            *reinterpret_cast<const float4*>(&fxp[idx]);
    }
    __syncthreads();

    for (int rrow = w * 4; rrow < w * 4 + 4; ++rrow) {
        float s = 0.f, s2 = 0.f;
#pragma unroll
        for (int c = lane; c < CC; c += 32) {
            const float v = sF[rrow * 264 + c];
            s += v; s2 += v * v;
        }
#pragma unroll
        for (int o = 16; o; o >>= 1) {
            s  += __shfl_xor_sync(0xffffffffu, s,  o);
            s2 += __shfl_xor_sync(0xffffffffu, s2, o);
        }
        const float mu = s * (1.f / CC);
        const float rstd = rsqrtf(s2 * (1.f / CC) - mu * mu + 1e-5f);
#pragma unroll
        for (int c = lane; c < CC; c += 32) {
            const float v = sF[rrow * 264 + c];
            sF[rrow * 264 + c] = (v - mu) * rstd * ln_g[c] + ln_b[c];
        }
    }
    __syncthreads();

    for (int idx = tid; idx < 8192; idx += 512) {
        const int row = idx >> 7, cp = idx & 127;
        const float2 v = *reinterpret_cast<const float2*>(&sF[row * 264 + cp * 2]);
        sA[row * 132 + cp] = pack2bf(v.x, v.y);
    }
    __syncthreads();

    const int jj_ = lane >> 3, rr_ = lane & 7;
    const int rowsel = (jj_ & 1) * 8 + rr_;
    const int colw   = (jj_ >> 1) * 4;
    const u32 aB = (u32)__cvta_generic_to_shared(sA);
    u32 offA[4];
#pragma unroll
    for (int mt = 0; mt < 4; ++mt)
        offA[mt] = (u32)(((mt * 16 + rowsel) * 132 + colw) * 4);

    float acc[4][4][4];
#pragma unroll
    for (int mt = 0; mt < 4; ++mt)
#pragma unroll
        for (int nt = 0; nt < 4; ++nt)
#pragma unroll
            for (int i = 0; i < 4; ++i) acc[mt][nt][i] = 0.f;

    const uint2* B2 = reinterpret_cast<const uint2*>(gi ? g_Bxs : g_Bfx);

    // single-pass bf16 GEMM: 64 rows x 32 cols per warp, reg prefetch
    {
        uint2 bb[4];
#pragma unroll
        for (int nt = 0; nt < 4; ++nt)
            bb[nt] = B2[(h * 4 + nt) * 32 + lane];
#pragma unroll 1
        for (int k16 = 0; k16 < 16; ++k16) {
            uint2 bn[4];
            if (k16 < 15) {
#pragma unroll
                for (int nt = 0; nt < 4; ++nt)
                    bn[nt] = B2[((k16 + 1) * 32 + h * 4 + nt) * 32 + lane];
            }
            u32 a[4][4];
#pragma unroll
            for (int mt = 0; mt < 4; ++mt)
                ldsm4(a[mt], aB + offA[mt] + (u32)(k16 * 32));
#pragma unroll
            for (int mt = 0; mt < 4; ++mt)
#pragma unroll
                for (int nt = 0; nt < 4; ++nt)
                    mma16816(acc[mt][nt], a[mt], bb[nt].x, bb[nt].y);
#pragma unroll
            for (int nt = 0; nt < 4; ++nt) bb[nt] = bn[nt];
        }
    }
    __syncthreads();   // sA dead -> region reusable as sW

    if (gi == 0) {
#pragma unroll
        for (int mt = 0; mt < 4; ++mt)
#pragma unroll
            for (int nt = 0; nt < 4; ++nt) {
                const int r0 = mt * 16 + g;
                const int c = h * 32 + nt * 8 + 2 * t;
                const float b0 = bfx[c], b1 = bfx[c + 1];
                *reinterpret_cast<float2*>(&sF[r0 * 264 + c]) =
                    make_float2(acc[mt][nt][0] + b0, acc[mt][nt][1] + b1);
                *reinterpret_cast<float2*>(&sF[(r0 + 8) * 264 + c]) =
                    make_float2(acc[mt][nt][2] + b0, acc[mt][nt][3] + b1);
            }
    } else {
        const float iv = sInvt[h];
#pragma unroll
        for (int mt = 0; mt < 4; ++mt)
#pragma unroll
            for (int nt = 0; nt < 4; ++nt) {
                const int c = h * 32 + nt * 8 + 2 * t;
                const float b0 = g_blog[c], b1 = g_blog[c + 1];
                acc[mt][nt][0] = (acc[mt][nt][0] + b0) * iv;
                acc[mt][nt][1] = (acc[mt][nt][1] + b1) * iv;
                acc[mt][nt][2] = (acc[mt][nt][2] + b0) * iv;
                acc[mt][nt][3] = (acc[mt][nt][3] + b1) * iv;
            }
#pragma unroll
        for (int mt = 0; mt < 4; ++mt)
#pragma unroll
            for (int rv = 0; rv < 2; ++rv) {
                float mx = -1e30f;
#pragma unroll
                for (int j = 0; j < 4; ++j) {
                    mx = fmaxf(mx, acc[mt][j][rv * 2]);
                    mx = fmaxf(mx, acc[mt][j][rv * 2 + 1]);
                }
                mx = fmaxf(mx, __shfl_xor_sync(0xffffffffu, mx, 1));
                mx = fmaxf(mx, __shfl_xor_sync(0xffffffffu, mx, 2));
                float sum = 0.f;
#pragma unroll
                for (int j = 0; j < 4; ++j) {
                    float e0 = __expf(acc[mt][j][rv * 2] - mx);
                    float e1 = __expf(acc[mt][j][rv * 2 + 1] - mx);
                    acc[mt][j][rv * 2] = e0;
                    acc[mt][j][rv * 2 + 1] = e1;
                    sum += e0 + e1;
                }
                sum += __shfl_xor_sync(0xffffffffu, sum, 1);
                sum += __shfl_xor_sync(0xffffffffu, sum, 2);
                const float inv = 1.0f / sum;
#pragma unroll
                for (int j = 0; j < 4; ++j) {
                    acc[mt][j][rv * 2] *= inv;
                    acc[mt][j][rv * 2 + 1] *= inv;
                }
            }
        u32* gw = reinterpret_cast<u32*>(g_w);
#pragma unroll
        for (int mt = 0; mt < 4; ++mt)
#pragma unroll
            for (int nt = 0; nt < 4; ++nt) {
                const int r0 = mt * 16 + g;
                const int c = h * 32 + nt * 8 + 2 * t;
                *reinterpret_cast<float2*>(&sW[r0 * 264 + c]) =
                    make_float2(acc[mt][nt][0], acc[mt][nt][1]);
                *reinterpret_cast<float2*>(&sW[(r0 + 8) * 264 + c]) =
                    make_float2(acc[mt][nt][2], acc[mt][nt][3]);
                size_t bi = (((size_t)batch * NN + n0 + r0) * 256 + c) >> 1;
                gw[bi] = pack2bf(acc[mt][nt][0], acc[mt][nt][1]);
                bi = (((size_t)batch * NN + n0 + r0 + 8) * 256 + c) >> 1;
                gw[bi] = pack2bf(acc[mt][nt][2], acc[mt][nt][3]);
            }
    }
    __syncthreads();

    // partial accumulation: warp = (half, head); combine halves via smem.
    {
        const int hh = w & 7;
        const int half = w >> 3;
        const int rbase = half * 32;
        float4 accT[8];
#pragma unroll
        for (int j = 0; j < 8; ++j) accT[j] = make_float4(0.f, 0.f, 0.f, 0.f);
        float accN = 0.f;
#pragma unroll 4
        for (int rr = 0; rr < 32; ++rr) {
            const int row = rbase + rr;
            const float wv = sW[row * 264 + hh * 32 + lane];
            accN += wv;
#pragma unroll
            for (int j = 0; j < 8; ++j) {
                const float4 f = *reinterpret_cast<const float4*>(
                    &sF[row * 264 + hh * 32 + j * 4]);
                accT[j].x = fmaf(wv, f.x, accT[j].x);
                accT[j].y = fmaf(wv, f.y, accT[j].y);
                accT[j].z = fmaf(wv, f.z, accT[j].z);
                accT[j].w = fmaf(wv, f.w, accT[j].w);
            }
        }
        __syncthreads();
        float* sX  = reinterpret_cast<float*>(smem);
        float* sXn = sX + 8192;
        if (half == 1) {
            float4* dst = reinterpret_cast<float4*>(&sX[(hh * 32 + lane) * 32]);
#pragma unroll
            for (int j = 0; j < 8; ++j) dst[j] = accT[j];
            sXn[hh * 32 + lane] = accN;
        }
        __syncthreads();
        if (half == 0) {
            const float4* src = reinterpret_cast<const float4*>(
                &sX[(hh * 32 + lane) * 32]);
            float4* pt = reinterpret_cast<float4*>(
                g_part_tok + ((size_t)blockIdx.x * 256 + hh * 32 + lane) * DD);
#pragma unroll
            for (int j = 0; j < 8; ++j) {
                float4 v = src[j];
                v.x += accT[j].x; v.y += accT[j].y;
                v.z += accT[j].z; v.w += accT[j].w;
                pt[j] = v;
            }
            g_part_norm[(size_t)blockIdx.x * 256 + hh * 32 + lane] =
                accN + sXn[hh * 32 + lane];
        }
    }
}

// ---------------- K2a: parallel partial reduce ---------------------------------
__global__ void __launch_bounds__(256)
k2a_reduce()
{
    __shared__ float red[8][33];
    __shared__ float rn[256];
    const int b  = blockIdx.x >> 8;
    const int hg = blockIdx.x & 255;
    const int tid = threadIdx.x;
    const int d = tid & 31, ck = tid >> 5;

    const float* base = g_part_tok + ((size_t)(b * PPB) * 256 + hg) * DD + d;
    float s = 0.f;
#pragma unroll 8
    for (int i = 0; i < PPB / 8; ++i)
        s += base[(size_t)(ck * (PPB / 8) + i) * (256 * DD)];
    red[ck][d] = s;

    float ns = 0.f;
#pragma unroll
    for (int j = 0; j < PPB / 256; ++j)
        ns += g_part_norm[(size_t)(b * PPB + tid * (PPB / 256) + j) * 256 + hg];
    rn[tid] = ns;
    __syncthreads();

    if (tid < 32) {
        float tot = 0.f;
#pragma unroll
        for (int c = 0; c < 8; ++c) tot += red[c][tid];
        g_tok_red[((size_t)b * 256 + hg) * DD + tid] = tot;
        float nsum = 0.f;
#pragma unroll
        for (int c = 0; c < 8; ++c) nsum += rn[tid + c * 32];
#pragma unroll
        for (int o = 16; o; o >>= 1) nsum += __shfl_xor_sync(0xffffffffu, nsum, o);
        if (tid == 0) g_norm_red[(size_t)b * 256 + hg] = nsum;
    }
}

// ---------------- K2b: attention + MLP + Wt frag image -------------------------
__global__ void __launch_bounds__(1024)
k2_tokens(const float* __restrict__ Wq, const float* __restrict__ Wk,
          const float* __restrict__ Wv,
          const float* __restrict__ tln_g, const float* __restrict__ tln_b,
          const float* __restrict__ W1, const float* __restrict__ b1,
          const float* __restrict__ W2, const float* __restrict__ b2,
          const float* __restrict__ Wo)
{
    const int b = blockIdx.x / HH;
    const int h = blockIdx.x % HH;
    const int tid = threadIdx.x;
    const int g = tid >> 5, d = tid & 31;

    __shared__ float s_st[GG][DD + 1];
    __shared__ float s_q[GG][DD + 1], s_k[GG][DD + 1], s_v[GG][DD + 1];
    __shared__ float s_attn[GG][GG + 1];
    __shared__ float s_h1[GG][4 * DD];
    __shared__ float s_tok2[GG][DD + 1];

    const float st = g_tok_red[((size_t)b * 256 + h * GG + g) * DD + d] /
                     (g_norm_red[(size_t)b * 256 + h * GG + g] + 1e-5f);
    s_st[g][d] = st;
    __syncthreads();

    float q = 0.f, kk = 0.f, vv = 0.f;
#pragma unroll
    for (int dd2 = 0; dd2 < DD; ++dd2) {
        const float sv = s_st[g][dd2];
        q  = fmaf(sv, Wq[dd2 * DD + d], q);
        kk = fmaf(sv, Wk[dd2 * DD + d], kk);
        vv = fmaf(sv, Wv[dd2 * DD + d], vv);
    }
    s_q[g][d] = q; s_k[g][d] = kk; s_v[g][d] = vv;
    __syncthreads();

    {
        const int kidx = d;
        float lg = 0.f;
#pragma unroll
        for (int dd2 = 0; dd2 < DD; ++dd2)
            lg = fmaf(s_q[g][dd2], s_k[kidx][dd2], lg);
        lg *= 0.17677669529663687f;
        float m = lg;
#pragma unroll
        for (int o = 16; o; o >>= 1) m = fmaxf(m, __shfl_xor_sync(0xffffffffu, m, o));
        const float e = __expf(lg - m);
        float ssum = e;
#pragma unroll
        for (int o = 16; o; o >>= 1) ssum += __shfl_xor_sync(0xffffffffu, ssum, o);
        s_attn[g][kidx] = e / ssum;
    }
    __syncthreads();

    float ot = st;
#pragma unroll
    for (int kidx = 0; kidx < GG; ++kidx)
        ot = fmaf(s_attn[g][kidx], s_v[kidx][d], ot);

    float s1 = ot, s2o = ot * ot;
#pragma unroll
    for (int o = 16; o; o >>= 1) {
        s1  += __shfl_xor_sync(0xffffffffu, s1,  o);
        s2o += __shfl_xor_sync(0xffffffffu, s2o, o);
    }
    const float mu = s1 * (1.f / DD);
    const float rstd = rsqrtf(s2o * (1.f / DD) - mu * mu + 1e-5f);
    const float hn = (ot - mu) * rstd * tln_g[d] + tln_b[d];
    __syncthreads();
    s_st[g][d] = hn;
    __syncthreads();

#pragma unroll
    for (int jj = 0; jj < 4; ++jj) {
        const int j = d + 32 * jj;
        float a = b1[j];
#pragma unroll
        for (int dd2 = 0; dd2 < DD; ++dd2)
            a = fmaf(s_st[g][dd2], W1[dd2 * (4 * DD) + j], a);
        a = 0.5f * a * (1.0f + erff(a * 0.70710678118654752f));
        s_h1[g][j] = a;
    }
    __syncthreads();

    float tk = b2[d];
#pragma unroll
    for (int j = 0; j < 4 * DD; ++j)
        tk = fmaf(s_h1[g][j], W2[j * DD + d], tk);
    tk += ot;
    s_tok2[g][d] = tk;
    __syncthreads();

    for (int idx = tid; idx < 4096; idx += 1024) {
        const int r = idx & 1;
        const int lane2 = (idx >> 1) & 31;
        const int nt = (idx >> 6) & 31;
        const int k16i = idx >> 11;
        const int t2 = lane2 & 3, g2 = lane2 >> 2;
        const int gl0 = k16i * 16 + r * 8 + 2 * t2;
        const int n = nt * 8 + g2;
        float v0 = 0.f, v1 = 0.f;
#pragma unroll
        for (int dd2 = 0; dd2 < DD; ++dd2) {
            const float wov = Wo[(h * DD + dd2) * CC + n];
            v0 = fmaf(s_tok2[gl0][dd2], wov, v0);
            v1 = fmaf(s_tok2[gl0 + 1][dd2], wov, v1);
        }
        const size_t oi = (size_t)b * 32768 +
            ((((size_t)(h * 2 + k16i) * 32 + nt) * 32 + lane2) * 2 + r);
        g_Wt[oi] = pack2bf(v0, v1);
    }
}

// ---------------- K3: out = w @ Wt + bo + LN(fx), TOK3=64, 2 CTAs/SM ----------
#define S3_MU    33792
#define S3_RS    (S3_MU + 256)
#define S3_TOTAL (S3_RS + 256)

__global__ void __launch_bounds__(512, 2)
k3_tc(const float* __restrict__ fx,
      const float* __restrict__ ln_g, const float* __restrict__ ln_b,
      const float* __restrict__ bo,  float* __restrict__ out)
{
    extern __shared__ char smem[];
    u32*   sA  = reinterpret_cast<u32*>(smem);
    float* sMu = reinterpret_cast<float*>(smem + S3_MU);
    float* sRs = reinterpret_cast<float*>(smem + S3_RS);

    const int tid  = threadIdx.x;
    const int w    = tid >> 5;
    const int lane = tid & 31;
    const int g    = lane >> 2, t = lane & 3;
    const int wr   = w >> 2;
    const int wn   = w & 3;
    const int batch = blockIdx.x / BLKS3;
    const int n0    = (blockIdx.x % BLKS3) * TOK3;

    {
        const u32* gw = reinterpret_cast<const u32*>(g_w) +
                        (((size_t)batch * NN + n0) * 256 >> 1);
        for (int idx = tid; idx < 64 * 128; idx += 512) {
            const int row = idx >> 7, cp = idx & 127;
            sA[row * 132 + cp] = gw[row * 128 + cp];
        }
    }

    for (int i = 0; i < 4; ++i) {
        const int row = w * 4 + i;
        const float* rp = fx + ((size_t)batch * NN + n0 + row) * CC + lane * 8;
        const float4 f1 = *reinterpret_cast<const float4*>(rp);
        const float4 f2 = *reinterpret_cast<const float4*>(rp + 4);
        float s = f1.x + f1.y + f1.z + f1.w + f2.x + f2.y + f2.z + f2.w;
        float s2 = f1.x * f1.x + f1.y * f1.y + f1.z * f1.z + f1.w * f1.w +
                   f2.x * f2.x + f2.y * f2.y + f2.z * f2.z + f2.w * f2.w;
#pragma unroll
        for (int o = 16; o; o >>= 1) {
            s  += __shfl_xor_sync(0xffffffffu, s,  o);
            s2 += __shfl_xor_sync(0xffffffffu, s2, o);
        }
        if (lane == 0) {
            const float mu = s * (1.f / CC);
            sMu[row] = mu;
            sRs[row] = rsqrtf(s2 * (1.f / CC) - mu * mu + 1e-5f);
        }
    }
    __syncthreads();

    const int jj_ = lane >> 3, rr_ = lane & 7;
    const int rowsel = (jj_ & 1) * 8 + rr_;
    const int colw   = (jj_ >> 1) * 4;
    const u32 aB = (u32)__cvta_generic_to_shared(sA);
    const u32 offA = (u32)(((wr * 16 + rowsel) * 132 + colw) * 4);

    const uint2* B = reinterpret_cast<const uint2*>(g_Wt + (size_t)batch * 32768);

#pragma unroll 1
    for (int ch = 0; ch < 2; ++ch) {
        float acc[4][4];
#pragma unroll
        for (int nt = 0; nt < 4; ++nt)
#pragma unroll
            for (int i = 0; i < 4; ++i) acc[nt][i] = 0.f;

        uint2 bb[4];
#pragma unroll
        for (int nt = 0; nt < 4; ++nt)
            bb[nt] = B[(ch * 16 + wn * 4 + nt) * 32 + lane];
#pragma unroll 1
        for (int k16 = 0; k16 < 16; ++k16) {
            uint2 bn[4];
            if (k16 < 15) {
#pragma unroll
                for (int nt = 0; nt < 4; ++nt)
                    bn[nt] = B[((k16 + 1) * 32 + ch * 16 + wn * 4 + nt) * 32 + lane];
            }
            u32 a[4];
            ldsm4(a, aB + offA + (u32)(k16 * 32));
#pragma unroll
            for (int nt = 0; nt < 4; ++nt)
                mma16816(acc[nt], a, bb[nt].x, bb[nt].y);
#pragma unroll
            for (int nt = 0; nt < 4; ++nt) bb[nt] = bn[nt];
        }

#pragma unroll
        for (int nt = 0; nt < 4; ++nt) {
            const int c = ch * 128 + wn * 32 + nt * 8 + 2 * t;
            const float bo0 = bo[c], bo1 = bo[c + 1];
            const float lg0 = ln_g[c], lg1 = ln_g[c + 1];
            const float lb0 = ln_b[c], lb1 = ln_b[c + 1];
#pragma unroll
            for (int rv = 0; rv < 2; ++rv) {
                const int row = wr * 16 + g + rv * 8;
                const size_t go = ((size_t)batch * NN + n0 + row) * 256 + c;
                const float2 fv = *reinterpret_cast<const float2*>(&fx[go]);
                const float mu = sMu[row], rs = sRs[row];
                float2 o;
                o.x = acc[nt][rv * 2]     + bo0 + (fv.x - mu) * rs * lg0 + lb0;
                o.y = acc[nt][rv * 2 + 1] + bo1 + (fv.y - mu) * rs * lg1 + lb1;
                *reinterpret_cast<float2*>(&out[go]) = o;
            }
        }
    }
}

// ---------------- launch -------------------------------------------------------
extern "C" void kernel_launch(void* const* d_in, const int* in_sizes, int n_in,
                              void* d_out, int out_size)
{
    const float* fx    = (const float*)d_in[0];
    const float* ln_g  = (const float*)d_in[1];
    const float* ln_b  = (const float*)d_in[2];
    const float* Wx    = (const float*)d_in[3];
    const float* bx    = (const float*)d_in[4];
    const float* Wfx   = (const float*)d_in[5];
    const float* bfx   = (const float*)d_in[6];
    const float* Ws    = (const float*)d_in[7];
    const float* bs    = (const float*)d_in[8];
    const float* tempp = (const float*)d_in[9];
    const float* Wq    = (const float*)d_in[10];
    const float* Wk    = (const float*)d_in[11];
    const float* Wv    = (const float*)d_in[12];
    const float* tln_g = (const float*)d_in[13];
    const float* tln_b = (const float*)d_in[14];
    const float* W1    = (const float*)d_in[15];
    const float* b1    = (const float*)d_in[16];
    const float* W2    = (const float*)d_in[17];
    const float* b2    = (const float*)d_in[18];
    const float* Wo    = (const float*)d_in[19];
    const float* bo    = (const float*)d_in[20];
    float* out = (float*)d_out;

    static int s_init = 0;
    if (!s_init) {
        cudaFuncSetAttribute(k1_dispatch, cudaFuncAttributeMaxDynamicSharedMemorySize, S1_TOTAL);
        cudaFuncSetAttribute(k3_tc, cudaFuncAttributeMaxDynamicSharedMemorySize, S3_TOTAL);
        s_init = 1;
    }

    k0_pack<<<256, 256>>>(Wx, Ws, bs, bx, Wfx);
    k1_dispatch<<<NBLK1, 512, S1_TOTAL>>>(fx, ln_g, ln_b, bfx, tempp);
    k2a_reduce<<<BB * 256, 256>>>();
    k2_tokens<<<BB * HH, 1024>>>(Wq, Wk, Wv, tln_g, tln_b, W1, b1, W2, b2, Wo);
    k3_tc<<<NBLK3, 512, S3_TOTAL>>>(fx, ln_g, ln_b, bo, out);
}

// round 17
// speedup vs baseline: 1.7223x; 1.1869x over previous
#include <cuda_runtime.h>
#include <cuda_bf16.h>
#include <math.h>
#include <cstdint>

#define BB 4
#define NN 32768
#define CC 256
#define HH 8
#define DD 32
#define GG 32
#define TOK1 64
#define BLKS1 (NN / TOK1)            // 512
#define NBLK1 (BB * BLKS1)           // 2048
#define PPB   BLKS1                  // 512 partials per batch
#define TOK3 64
#define BLKS3 (NN / TOK3)            // 512
#define NBLK3 (BB * BLKS3)           // 2048

typedef unsigned int u32;
typedef unsigned short u16;

// ---------------- device scratch ---------------------------------------------
__device__ u32   g_Bxs[32768];                      // WxWs frag image (bf16x2)
__device__ u32   g_Bfx[32768];                      // Wfx frag image
__device__ float g_blog[256];
__device__ u16   g_w[(size_t)BB * NN * 256];        // slice_w bf16 [b][n][hg]
__device__ float g_part_tok[(size_t)NBLK1 * 256 * DD];
__device__ float g_part_norm[(size_t)NBLK1 * 256];
__device__ float g_tok_red[(size_t)BB * 256 * DD];
__device__ float g_norm_red[(size_t)BB * 256];
__device__ u32   g_Wt[(size_t)BB * 32768];          // Wt frag image per batch

// ---------------- helpers -----------------------------------------------------
__device__ __forceinline__ u32 pack2bf(float x, float y) {
    __nv_bfloat162 h = __floats2bfloat162_rn(x, y);
    return *reinterpret_cast<u32*>(&h);
}
__device__ __forceinline__ u16 bf16of(float x) {
    __nv_bfloat16 h = __float2bfloat16_rn(x);
    return *reinterpret_cast<u16*>(&h);
}
__device__ __forceinline__ void mma16816(float* d, const u32* a, u32 b0, u32 b1) {
    asm volatile(
        "mma.sync.aligned.m16n8k16.row.col.f32.bf16.bf16.f32 "
        "{%0,%1,%2,%3}, {%4,%5,%6,%7}, {%8,%9}, {%0,%1,%2,%3};"
        : "+f"(d[0]), "+f"(d[1]), "+f"(d[2]), "+f"(d[3])
        : "r"(a[0]), "r"(a[1]), "r"(a[2]), "r"(a[3]), "r"(b0), "r"(b1));
}
__device__ __forceinline__ void ldsm4(u32* r, u32 saddr) {
    asm volatile(
        "ldmatrix.sync.aligned.m8n8.x4.shared.b16 {%0,%1,%2,%3}, [%4];"
        : "=r"(r[0]), "=r"(r[1]), "=r"(r[2]), "=r"(r[3]) : "r"(saddr));
}

// ---------------- K0: pack weight fragment images ----------------------------
__global__ void __launch_bounds__(256)
k0_pack(const float* __restrict__ Wx, const float* __restrict__ Ws,
        const float* __restrict__ bs, const float* __restrict__ bx,
        const float* __restrict__ Wfx)
{
    const int pid = blockIdx.x * 256 + threadIdx.x;
    const int img = pid >> 15;
    const int p = pid & 32767;
    const int r = p & 1, lane = (p >> 1) & 31, nt = (p >> 6) & 31, k16 = p >> 11;
    const int t = lane & 3, g = lane >> 2;
    const int k = k16 * 16 + r * 8 + 2 * t;
    const int n = nt * 8 + g;
    float v0, v1;
    if (img == 0) {
        const int h = n >> 5, gg = n & 31;
        float s0 = 0.f, s1 = 0.f;
#pragma unroll
        for (int d = 0; d < DD; ++d) {
            const float w = Ws[d * GG + gg];
            s0 = fmaf(Wx[k * 256 + h * 32 + d], w, s0);
            s1 = fmaf(Wx[(k + 1) * 256 + h * 32 + d], w, s1);
        }
        v0 = s0; v1 = s1;
    } else {
        v0 = Wfx[k * 256 + n];
        v1 = Wfx[(k + 1) * 256 + n];
    }
    const u32 hv = pack2bf(v0, v1);
    if (img == 0) g_Bxs[p] = hv;
    else          g_Bfx[p] = hv;

    if (blockIdx.x == 0) {
        const int hg = threadIdx.x;
        const int h = hg >> 5, gg = hg & 31;
        float s = bs[gg];
#pragma unroll
        for (int d = 0; d < DD; ++d)
            s = fmaf(bx[h * 32 + d], Ws[d * GG + gg], s);
        g_blog[hg] = s;
    }
}

// ---------------- K1: LN + GEMMs + softmax + MMA partial accumulation ---------
// smem layout:
//   [0, 73728): phase1-2: sF f32[64][264] (67584); phase4+: wT u16[256][72]
//               at [0,36864) and fT u16[256][72] at [36864,73728)
//   [73728, 107520): sA u32[64][132] bf16x2 GEMM A image
//   [107520, +64): sInvt
#define S1_FT    36864
#define S1_SA    73728
#define S1_INVT  107520
#define S1_TOTAL (S1_INVT + 64)

__global__ void __launch_bounds__(512, 1)
k1_dispatch(const float* __restrict__ fx,
            const float* __restrict__ ln_g, const float* __restrict__ ln_b,
            const float* __restrict__ bfx,  const float* __restrict__ tempp)
{
    extern __shared__ char smem[];
    float* sF    = reinterpret_cast<float*>(smem);
    u16*   wT16  = reinterpret_cast<u16*>(smem);
    u16*   fT16  = reinterpret_cast<u16*>(smem + S1_FT);
    const u32* fT32 = reinterpret_cast<const u32*>(smem + S1_FT);
    u32*   sA    = reinterpret_cast<u32*>(smem + S1_SA);
    float* sInvt = reinterpret_cast<float*>(smem + S1_INVT);

    const int tid  = threadIdx.x;
    const int w    = tid >> 5;
    const int lane = tid & 31;
    const int g    = lane >> 2, t = lane & 3;
    const int gi   = w >> 3;              // 0: fx_mid GEMM, 1: logits GEMM
    const int h    = w & 7;               // head
    const int batch = blockIdx.x / BLKS1;
    const int n0    = (blockIdx.x % BLKS1) * TOK1;

    if (tid < HH) sInvt[tid] = 1.0f / tempp[tid];

    const float* fxp = fx + ((size_t)batch * NN + n0) * CC;
    for (int idx = tid * 4; idx < TOK1 * CC; idx += 2048) {
        const int row = idx >> 8, col = idx & 255;
        *reinterpret_cast<float4*>(&sF[row * 264 + col]) =
            *reinterpret_cast<const float4*>(&fxp[idx]);
    }
    __syncthreads();

    for (int rrow = w * 4; rrow < w * 4 + 4; ++rrow) {
        float s = 0.f, s2 = 0.f;
#pragma unroll
        for (int c = lane; c < CC; c += 32) {
            const float v = sF[rrow * 264 + c];
            s += v; s2 += v * v;
        }
#pragma unroll
        for (int o = 16; o; o >>= 1) {
            s  += __shfl_xor_sync(0xffffffffu, s,  o);
            s2 += __shfl_xor_sync(0xffffffffu, s2, o);
        }
        const float mu = s * (1.f / CC);
        const float rstd = rsqrtf(s2 * (1.f / CC) - mu * mu + 1e-5f);
#pragma unroll
        for (int c = lane; c < CC; c += 32) {
            const float v = sF[rrow * 264 + c];
            sF[rrow * 264 + c] = (v - mu) * rstd * ln_g[c] + ln_b[c];
        }
    }
    __syncthreads();

    for (int idx = tid; idx < 8192; idx += 512) {
        const int row = idx >> 7, cp = idx & 127;
        const float2 v = *reinterpret_cast<const float2*>(&sF[row * 264 + cp * 2]);
        sA[row * 132 + cp] = pack2bf(v.x, v.y);
    }
    __syncthreads();   // after this, sF region is dead (becomes wT/fT)

    const int jj_ = lane >> 3, rr_ = lane & 7;
    const int rowsel = (jj_ & 1) * 8 + rr_;
    const int colw   = (jj_ >> 1) * 4;
    const u32 aB  = (u32)__cvta_generic_to_shared(sA);
    const u32 wtB = (u32)__cvta_generic_to_shared(smem);
    u32 offA[4];
#pragma unroll
    for (int mt = 0; mt < 4; ++mt)
        offA[mt] = (u32)(((mt * 16 + rowsel) * 132 + colw) * 4);

    float acc[4][4][4];
#pragma unroll
    for (int mt = 0; mt < 4; ++mt)
#pragma unroll
        for (int nt = 0; nt < 4; ++nt)
#pragma unroll
            for (int i = 0; i < 4; ++i) acc[mt][nt][i] = 0.f;

    const uint2* B2 = reinterpret_cast<const uint2*>(gi ? g_Bxs : g_Bfx);

    // single-pass bf16 GEMM: 64 rows x 32 cols per warp, reg prefetch
    {
        uint2 bb[4];
#pragma unroll
        for (int nt = 0; nt < 4; ++nt)
            bb[nt] = B2[(h * 4 + nt) * 32 + lane];
#pragma unroll 1
        for (int k16 = 0; k16 < 16; ++k16) {
            uint2 bn[4];
            if (k16 < 15) {
#pragma unroll
                for (int nt = 0; nt < 4; ++nt)
                    bn[nt] = B2[((k16 + 1) * 32 + h * 4 + nt) * 32 + lane];
            }
            u32 a[4][4];
#pragma unroll
            for (int mt = 0; mt < 4; ++mt)
                ldsm4(a[mt], aB + offA[mt] + (u32)(k16 * 32));
#pragma unroll
            for (int mt = 0; mt < 4; ++mt)
#pragma unroll
                for (int nt = 0; nt < 4; ++nt)
                    mma16816(acc[mt][nt], a[mt], bb[nt].x, bb[nt].y);
#pragma unroll
            for (int nt = 0; nt < 4; ++nt) bb[nt] = bn[nt];
        }
    }
    // no barrier needed: epilogue writes go to the dead sF region

    if (gi == 0) {
        // fx_mid + bias -> transposed bf16 image fT[hd][row]
#pragma unroll
        for (int mt = 0; mt < 4; ++mt)
#pragma unroll
            for (int nt = 0; nt < 4; ++nt) {
                const int c = h * 32 + nt * 8 + 2 * t;
                const int r0 = mt * 16 + g;
                const float b0 = bfx[c], b1 = bfx[c + 1];
                fT16[c * 72 + r0]           = bf16of(acc[mt][nt][0] + b0);
                fT16[(c + 1) * 72 + r0]     = bf16of(acc[mt][nt][1] + b1);
                fT16[c * 72 + r0 + 8]       = bf16of(acc[mt][nt][2] + b0);
                fT16[(c + 1) * 72 + r0 + 8] = bf16of(acc[mt][nt][3] + b1);
            }
    } else {
        const float iv = sInvt[h];
#pragma unroll
        for (int mt = 0; mt < 4; ++mt)
#pragma unroll
            for (int nt = 0; nt < 4; ++nt) {
                const int c = h * 32 + nt * 8 + 2 * t;
                const float b0 = g_blog[c], b1 = g_blog[c + 1];
                acc[mt][nt][0] = (acc[mt][nt][0] + b0) * iv;
                acc[mt][nt][1] = (acc[mt][nt][1] + b1) * iv;
                acc[mt][nt][2] = (acc[mt][nt][2] + b0) * iv;
                acc[mt][nt][3] = (acc[mt][nt][3] + b1) * iv;
            }
#pragma unroll
        for (int mt = 0; mt < 4; ++mt)
#pragma unroll
            for (int rv = 0; rv < 2; ++rv) {
                float mx = -1e30f;
#pragma unroll
                for (int j = 0; j < 4; ++j) {
                    mx = fmaxf(mx, acc[mt][j][rv * 2]);
                    mx = fmaxf(mx, acc[mt][j][rv * 2 + 1]);
                }
                mx = fmaxf(mx, __shfl_xor_sync(0xffffffffu, mx, 1));
                mx = fmaxf(mx, __shfl_xor_sync(0xffffffffu, mx, 2));
                float sum = 0.f;
#pragma unroll
                for (int j = 0; j < 4; ++j) {
                    float e0 = __expf(acc[mt][j][rv * 2] - mx);
                    float e1 = __expf(acc[mt][j][rv * 2 + 1] - mx);
                    acc[mt][j][rv * 2] = e0;
                    acc[mt][j][rv * 2 + 1] = e1;
                    sum += e0 + e1;
                }
                sum += __shfl_xor_sync(0xffffffffu, sum, 1);
                sum += __shfl_xor_sync(0xffffffffu, sum, 2);
                const float inv = 1.0f / sum;
#pragma unroll
                for (int j = 0; j < 4; ++j) {
                    acc[mt][j][rv * 2] *= inv;
                    acc[mt][j][rv * 2 + 1] *= inv;
                }
            }
        // write w: bf16 to gmem + transposed image wT[hg][row]
        u32* gw = reinterpret_cast<u32*>(g_w);
#pragma unroll
        for (int mt = 0; mt < 4; ++mt)
#pragma unroll
            for (int nt = 0; nt < 4; ++nt) {
                const int c = h * 32 + nt * 8 + 2 * t;
                const int r0 = mt * 16 + g;
                wT16[c * 72 + r0]           = bf16of(acc[mt][nt][0]);
                wT16[(c + 1) * 72 + r0]     = bf16of(acc[mt][nt][1]);
                wT16[c * 72 + r0 + 8]       = bf16of(acc[mt][nt][2]);
                wT16[(c + 1) * 72 + r0 + 8] = bf16of(acc[mt][nt][3]);
                size_t bi = (((size_t)batch * NN + n0 + r0) * 256 + c) >> 1;
                gw[bi] = pack2bf(acc[mt][nt][0], acc[mt][nt][1]);
                bi = (((size_t)batch * NN + n0 + r0 + 8) * 256 + c) >> 1;
                gw[bi] = pack2bf(acc[mt][nt][2], acc[mt][nt][3]);
            }
        // norms from fp32 w registers (full 64 rows in this warp)
#pragma unroll
        for (int nt = 0; nt < 4; ++nt)
#pragma unroll
            for (int par = 0; par < 2; ++par) {
                float s = 0.f;
#pragma unroll
                for (int mt = 0; mt < 4; ++mt)
                    s += acc[mt][nt][par] + acc[mt][nt][par + 2];
                s += __shfl_xor_sync(0xffffffffu, s, 4);
                s += __shfl_xor_sync(0xffffffffu, s, 8);
                s += __shfl_xor_sync(0xffffffffu, s, 16);
                if (g == 0)
                    g_part_norm[(size_t)blockIdx.x * 256 + h * 32 + nt * 8 + 2 * t + par] = s;
            }
    }
    __syncthreads();   // wT/fT images complete

    // MMA partial accumulation: P[g][d] = sum_row wT[hg][row] * fT[hd][row]
    // warp = (head h2, d-half dh): M=32 (g), N=16 (d-half), K=64 (rows)
    {
        const int h2 = w & 7;
        const int dh = w >> 3;
        float accP[2][2][4];
#pragma unroll
        for (int mt = 0; mt < 2; ++mt)
#pragma unroll
            for (int nt = 0; nt < 2; ++nt)
#pragma unroll
                for (int i = 0; i < 4; ++i) accP[mt][nt][i] = 0.f;

#pragma unroll
        for (int kt = 0; kt < 4; ++kt) {
            u32 a[2][4];
#pragma unroll
            for (int mt = 0; mt < 2; ++mt)
                ldsm4(a[mt], wtB + (u32)((((h2 * 32 + mt * 16 + rowsel) * 36) + kt * 8 + colw) * 4));
            uint2 b[2];
#pragma unroll
            for (int nt = 0; nt < 2; ++nt) {
                const int n = h2 * 32 + dh * 16 + nt * 8 + g;   // FIX: global hd row
                b[nt].x = fT32[n * 36 + kt * 8 + t];
                b[nt].y = fT32[n * 36 + kt * 8 + 4 + t];
            }
#pragma unroll
            for (int mt = 0; mt < 2; ++mt)
#pragma unroll
                for (int nt = 0; nt < 2; ++nt)
                    mma16816(accP[mt][nt], a[mt], b[nt].x, b[nt].y);
        }
#pragma unroll
        for (int mt = 0; mt < 2; ++mt)
#pragma unroll
            for (int nt = 0; nt < 2; ++nt) {
                const int gg = mt * 16 + g;
                const int dd = dh * 16 + nt * 8 + 2 * t;
                float* base = g_part_tok +
                    ((size_t)blockIdx.x * 256 + h2 * 32 + gg) * DD + dd;
                *reinterpret_cast<float2*>(base) =
                    make_float2(accP[mt][nt][0], accP[mt][nt][1]);
                float* base2 = g_part_tok +
                    ((size_t)blockIdx.x * 256 + h2 * 32 + gg + 8) * DD + dd;
                *reinterpret_cast<float2*>(base2) =
                    make_float2(accP[mt][nt][2], accP[mt][nt][3]);
            }
    }
}

// ---------------- K2a: parallel partial reduce ---------------------------------
__global__ void __launch_bounds__(256)
k2a_reduce()
{
    __shared__ float red[8][33];
    __shared__ float rn[256];
    const int b  = blockIdx.x >> 8;
    const int hg = blockIdx.x & 255;
    const int tid = threadIdx.x;
    const int d = tid & 31, ck = tid >> 5;

    const float* base = g_part_tok + ((size_t)(b * PPB) * 256 + hg) * DD + d;
    float s = 0.f;
#pragma unroll 8
    for (int i = 0; i < PPB / 8; ++i)
        s += base[(size_t)(ck * (PPB / 8) + i) * (256 * DD)];
    red[ck][d] = s;

    float ns = 0.f;
#pragma unroll
    for (int j = 0; j < PPB / 256; ++j)
        ns += g_part_norm[(size_t)(b * PPB + tid * (PPB / 256) + j) * 256 + hg];
    rn[tid] = ns;
    __syncthreads();

    if (tid < 32) {
        float tot = 0.f;
#pragma unroll
        for (int c = 0; c < 8; ++c) tot += red[c][tid];
        g_tok_red[((size_t)b * 256 + hg) * DD + tid] = tot;
        float nsum = 0.f;
#pragma unroll
        for (int c = 0; c < 8; ++c) nsum += rn[tid + c * 32];
#pragma unroll
        for (int o = 16; o; o >>= 1) nsum += __shfl_xor_sync(0xffffffffu, nsum, o);
        if (tid == 0) g_norm_red[(size_t)b * 256 + hg] = nsum;
    }
}

// ---------------- K2b: attention + MLP + Wt frag image -------------------------
__global__ void __launch_bounds__(1024)
k2_tokens(const float* __restrict__ Wq, const float* __restrict__ Wk,
          const float* __restrict__ Wv,
          const float* __restrict__ tln_g, const float* __restrict__ tln_b,
          const float* __restrict__ W1, const float* __restrict__ b1,
          const float* __restrict__ W2, const float* __restrict__ b2,
          const float* __restrict__ Wo)
{
    const int b = blockIdx.x / HH;
    const int h = blockIdx.x % HH;
    const int tid = threadIdx.x;
    const int g = tid >> 5, d = tid & 31;

    __shared__ float s_st[GG][DD + 1];
    __shared__ float s_q[GG][DD + 1], s_k[GG][DD + 1], s_v[GG][DD + 1];
    __shared__ float s_attn[GG][GG + 1];
    __shared__ float s_h1[GG][4 * DD];
    __shared__ float s_tok2[GG][DD + 1];

    const float st = g_tok_red[((size_t)b * 256 + h * GG + g) * DD + d] /
                     (g_norm_red[(size_t)b * 256 + h * GG + g] + 1e-5f);
    s_st[g][d] = st;
    __syncthreads();

    float q = 0.f, kk = 0.f, vv = 0.f;
#pragma unroll
    for (int dd2 = 0; dd2 < DD; ++dd2) {
        const float sv = s_st[g][dd2];
        q  = fmaf(sv, Wq[dd2 * DD + d], q);
        kk = fmaf(sv, Wk[dd2 * DD + d], kk);
        vv = fmaf(sv, Wv[dd2 * DD + d], vv);
    }
    s_q[g][d] = q; s_k[g][d] = kk; s_v[g][d] = vv;
    __syncthreads();

    {
        const int kidx = d;
        float lg = 0.f;
#pragma unroll
        for (int dd2 = 0; dd2 < DD; ++dd2)
            lg = fmaf(s_q[g][dd2], s_k[kidx][dd2], lg);
        lg *= 0.17677669529663687f;
        float m = lg;
#pragma unroll
        for (int o = 16; o; o >>= 1) m = fmaxf(m, __shfl_xor_sync(0xffffffffu, m, o));
        const float e = __expf(lg - m);
        float ssum = e;
#pragma unroll
        for (int o = 16; o; o >>= 1) ssum += __shfl_xor_sync(0xffffffffu, ssum, o);
        s_attn[g][kidx] = e / ssum;
    }
    __syncthreads();

    float ot = st;
#pragma unroll
    for (int kidx = 0; kidx < GG; ++kidx)
        ot = fmaf(s_attn[g][kidx], s_v[kidx][d], ot);

    float s1 = ot, s2o = ot * ot;
#pragma unroll
    for (int o = 16; o; o >>= 1) {
        s1  += __shfl_xor_sync(0xffffffffu, s1,  o);
        s2o += __shfl_xor_sync(0xffffffffu, s2o, o);
    }
    const float mu = s1 * (1.f / DD);
    const float rstd = rsqrtf(s2o * (1.f / DD) - mu * mu + 1e-5f);
    const float hn = (ot - mu) * rstd * tln_g[d] + tln_b[d];
    __syncthreads();
    s_st[g][d] = hn;
    __syncthreads();

#pragma unroll
    for (int jj = 0; jj < 4; ++jj) {
        const int j = d + 32 * jj;
        float a = b1[j];
#pragma unroll
        for (int dd2 = 0; dd2 < DD; ++dd2)
            a = fmaf(s_st[g][dd2], W1[dd2 * (4 * DD) + j], a);
        a = 0.5f * a * (1.0f + erff(a * 0.70710678118654752f));
        s_h1[g][j] = a;
    }
    __syncthreads();

    float tk = b2[d];
#pragma unroll
    for (int j = 0; j < 4 * DD; ++j)
        tk = fmaf(s_h1[g][j], W2[j * DD + d], tk);
    tk += ot;
    s_tok2[g][d] = tk;
    __syncthreads();

    for (int idx = tid; idx < 4096; idx += 1024) {
        const int r = idx & 1;
        const int lane2 = (idx >> 1) & 31;
        const int nt = (idx >> 6) & 31;
        const int k16i = idx >> 11;
        const int t2 = lane2 & 3, g2 = lane2 >> 2;
        const int gl0 = k16i * 16 + r * 8 + 2 * t2;
        const int n = nt * 8 + g2;
        float v0 = 0.f, v1 = 0.f;
#pragma unroll
        for (int dd2 = 0; dd2 < DD; ++dd2) {
            const float wov = Wo[(h * DD + dd2) * CC + n];
            v0 = fmaf(s_tok2[gl0][dd2], wov, v0);
            v1 = fmaf(s_tok2[gl0 + 1][dd2], wov, v1);
        }
        const size_t oi = (size_t)b * 32768 +
            ((((size_t)(h * 2 + k16i) * 32 + nt) * 32 + lane2) * 2 + r);
        g_Wt[oi] = pack2bf(v0, v1);
    }
}

// ---------------- K3: out = w @ Wt + bo + LN(fx), fx cached in smem -----------
// smem: sA u32[64][132] @0 | sFx f32[64][264] @33792 | sMu @101376 | sRs
#define S3_FX    33792
#define S3_MU    (S3_FX + 64 * 264 * 4)      // 101376
#define S3_RS    (S3_MU + 256)
#define S3_TOTAL (S3_RS + 256)

__global__ void __launch_bounds__(512, 2)
k3_tc(const float* __restrict__ fx,
      const float* __restrict__ ln_g, const float* __restrict__ ln_b,
      const float* __restrict__ bo,  float* __restrict__ out)
{
    extern __shared__ char smem[];
    u32*   sA  = reinterpret_cast<u32*>(smem);
    float* sFx = reinterpret_cast<float*>(smem + S3_FX);
    float* sMu = reinterpret_cast<float*>(smem + S3_MU);
    float* sRs = reinterpret_cast<float*>(smem + S3_RS);

    const int tid  = threadIdx.x;
    const int w    = tid >> 5;
    const int lane = tid & 31;
    const int g    = lane >> 2, t = lane & 3;
    const int wr   = w >> 2;
    const int wn   = w & 3;
    const int batch = blockIdx.x / BLKS3;
    const int n0    = (blockIdx.x % BLKS3) * TOK3;

    {
        const u32* gw = reinterpret_cast<const u32*>(g_w) +
                        (((size_t)batch * NN + n0) * 256 >> 1);
        for (int idx = tid; idx < 64 * 128; idx += 512) {
            const int row = idx >> 7, cp = idx & 127;
            sA[row * 132 + cp] = gw[row * 128 + cp];
        }
    }
    {
        const float* fxp = fx + ((size_t)batch * NN + n0) * CC;
        for (int idx = tid * 4; idx < TOK3 * CC; idx += 2048) {
            const int row = idx >> 8, col = idx & 255;
            *reinterpret_cast<float4*>(&sFx[row * 264 + col]) =
                *reinterpret_cast<const float4*>(&fxp[idx]);
        }
    }
    __syncthreads();

    for (int i = 0; i < 4; ++i) {
        const int row = w * 4 + i;
        float s = 0.f, s2 = 0.f;
#pragma unroll
        for (int c = lane; c < CC; c += 32) {
            const float v = sFx[row * 264 + c];
            s += v; s2 += v * v;
        }
#pragma unroll
        for (int o = 16; o; o >>= 1) {
            s  += __shfl_xor_sync(0xffffffffu, s,  o);
            s2 += __shfl_xor_sync(0xffffffffu, s2, o);
        }
        if (lane == 0) {
            const float mu = s * (1.f / CC);
            sMu[row] = mu;
            sRs[row] = rsqrtf(s2 * (1.f / CC) - mu * mu + 1e-5f);
        }
    }
    __syncthreads();

    const int jj_ = lane >> 3, rr_ = lane & 7;
    const int rowsel = (jj_ & 1) * 8 + rr_;
    const int colw   = (jj_ >> 1) * 4;
    const u32 aB = (u32)__cvta_generic_to_shared(sA);
    const u32 offA = (u32)(((wr * 16 + rowsel) * 132 + colw) * 4);

    const uint2* B = reinterpret_cast<const uint2*>(g_Wt + (size_t)batch * 32768);

#pragma unroll 1
    for (int ch = 0; ch < 2; ++ch) {
        float acc[4][4];
#pragma unroll
        for (int nt = 0; nt < 4; ++nt)
#pragma unroll
            for (int i = 0; i < 4; ++i) acc[nt][i] = 0.f;

        uint2 bb[4];
#pragma unroll
        for (int nt = 0; nt < 4; ++nt)
            bb[nt] = B[(ch * 16 + wn * 4 + nt) * 32 + lane];
#pragma unroll 1
        for (int k16 = 0; k16 < 16; ++k16) {
            uint2 bn[4];
            if (k16 < 15) {
#pragma unroll
                for (int nt = 0; nt < 4; ++nt)
                    bn[nt] = B[((k16 + 1) * 32 + ch * 16 + wn * 4 + nt) * 32 + lane];
            }
            u32 a[4];
            ldsm4(a, aB + offA + (u32)(k16 * 32));
#pragma unroll
            for (int nt = 0; nt < 4; ++nt)
                mma16816(acc[nt], a, bb[nt].x, bb[nt].y);
#pragma unroll
            for (int nt = 0; nt < 4; ++nt) bb[nt] = bn[nt];
        }

#pragma unroll
        for (int nt = 0; nt < 4; ++nt) {
            const int c = ch * 128 + wn * 32 + nt * 8 + 2 * t;
            const float bo0 = bo[c], bo1 = bo[c + 1];
            const float lg0 = ln_g[c], lg1 = ln_g[c + 1];
            const float lb0 = ln_b[c], lb1 = ln_b[c + 1];
#pragma unroll
            for (int rv = 0; rv < 2; ++rv) {
                const int row = wr * 16 + g + rv * 8;
                const size_t go = ((size_t)batch * NN + n0 + row) * 256 + c;
                const float2 fv = *reinterpret_cast<const float2*>(&sFx[row * 264 + c]);
                const float mu = sMu[row], rs = sRs[row];
                float2 o;
                o.x = acc[nt][rv * 2]     + bo0 + (fv.x - mu) * rs * lg0 + lb0;
                o.y = acc[nt][rv * 2 + 1] + bo1 + (fv.y - mu) * rs * lg1 + lb1;
                *reinterpret_cast<float2*>(&out[go]) = o;
            }
        }
    }
}

// ---------------- launch -------------------------------------------------------
extern "C" void kernel_launch(void* const* d_in, const int* in_sizes, int n_in,
                              void* d_out, int out_size)
{
    const float* fx    = (const float*)d_in[0];
    const float* ln_g  = (const float*)d_in[1];
    const float* ln_b  = (const float*)d_in[2];
    const float* Wx    = (const float*)d_in[3];
    const float* bx    = (const float*)d_in[4];
    const float* Wfx   = (const float*)d_in[5];
    const float* bfx   = (const float*)d_in[6];
    const float* Ws    = (const float*)d_in[7];
    const float* bs    = (const float*)d_in[8];
    const float* tempp = (const float*)d_in[9];
    const float* Wq    = (const float*)d_in[10];
    const float* Wk    = (const float*)d_in[11];
    const float* Wv    = (const float*)d_in[12];
    const float* tln_g = (const float*)d_in[13];
    const float* tln_b = (const float*)d_in[14];
    const float* W1    = (const float*)d_in[15];
    const float* b1    = (const float*)d_in[16];
    const float* W2    = (const float*)d_in[17];
    const float* b2    = (const float*)d_in[18];
    const float* Wo    = (const float*)d_in[19];
    const float* bo    = (const float*)d_in[20];
    float* out = (float*)d_out;

    static int s_init = 0;
    if (!s_init) {
        cudaFuncSetAttribute(k1_dispatch, cudaFuncAttributeMaxDynamicSharedMemorySize, S1_TOTAL);
        cudaFuncSetAttribute(k3_tc, cudaFuncAttributeMaxDynamicSharedMemorySize, S3_TOTAL);
        s_init = 1;
    }

    k0_pack<<<256, 256>>>(Wx, Ws, bs, bx, Wfx);
    k1_dispatch<<<NBLK1, 512, S1_TOTAL>>>(fx, ln_g, ln_b, bfx, tempp);
    k2a_reduce<<<BB * 256, 256>>>();
    k2_tokens<<<BB * HH, 1024>>>(Wq, Wk, Wv, tln_g, tln_b, W1, b1, W2, b2, Wo);
    k3_tc<<<NBLK3, 512, S3_TOTAL>>>(fx, ln_g, ln_b, bo, out);
}